// round 12
// baseline (speedup 1.0000x reference)
#include <cuda_runtime.h>
#include <cstdint>

// R11: fused persistent PatchGram, 18KB work units, 5 CTAs/SM.
// Unit = one layer0 patch (C=512, K=8, 64 fr rows) or half a layer1 patch
// (512 contiguous channels, K=16, 32 fr rows). Epilogue fires when a patch's
// fr[64][9] is complete.
//   fr[cr][p]  = mean over K consecutive channels
//   sg[g][p]   = sum of 4 consecutive fr rows
//   out[n][layer][cr*16+g] = (1/36) * sum_p fr[cr][p] * sg[g][p]

__device__ __forceinline__ uint32_t smem_u32(const void* p) {
    return (uint32_t)__cvta_generic_to_shared(p);
}
__device__ __forceinline__ void mbar_init(uint32_t a, uint32_t cnt) {
    asm volatile("mbarrier.init.shared.b64 [%0], %1;" :: "r"(a), "r"(cnt) : "memory");
}
__device__ __forceinline__ void mbar_expect_tx(uint32_t a, uint32_t bytes) {
    asm volatile("mbarrier.arrive.expect_tx.shared.b64 _, [%0], %1;"
                 :: "r"(a), "r"(bytes) : "memory");
}
__device__ __forceinline__ void mbar_wait(uint32_t a, uint32_t phase) {
    asm volatile(
        "{\n\t"
        ".reg .pred p;\n\t"
        "WAIT_%=:\n\t"
        "mbarrier.try_wait.parity.acquire.cta.shared::cta.b64 p, [%0], %1, 0x989680;\n\t"
        "@p bra DONE_%=;\n\t"
        "bra WAIT_%=;\n\t"
        "DONE_%=:\n\t"
        "}"
        :: "r"(a), "r"(phase) : "memory");
}
__device__ __forceinline__ void bulk_g2s(uint32_t dst_smem, const void* src_gmem,
                                         uint32_t bytes, uint32_t mbar) {
    asm volatile(
        "cp.async.bulk.shared::cluster.global.mbarrier::complete_tx::bytes "
        "[%0], [%1], %2, [%3];"
        :: "r"(dst_smem), "l"(src_gmem), "r"(bytes), "r"(mbar) : "memory");
}

__global__ __launch_bounds__(256)
void fused_gram_kernel(const float* __restrict__ feat0,
                       const float* __restrict__ feat1,
                       float* __restrict__ out, int N)
{
    constexpr int NFU = 4608;                  // floats per 18KB unit
    constexpr uint32_t BYTES = NFU * 4u;
    constexpr int S = 2;

    extern __shared__ float buf[];             // [S][NFU] = 36 KB
    __shared__ float fr[64][12];
    __shared__ float sg[16][12];
    __shared__ alignas(8) unsigned long long mbar_s[S];

    const int tid = threadIdx.x;
    const int b   = blockIdx.x;
    const int G   = gridDim.x;

    const int n1 = (N > b) ? (N - b + G - 1) / G : 0;   // strided L1 patches
    const int n0 = (N > b) ? (N - b + G - 1) / G : 0;   // strided L0 patches
    const int NU = 2 * n1 + n0;                          // total 18KB units

    const uint32_t bufa = smem_u32(buf);
    const uint32_t mb0 = smem_u32(&mbar_s[0]);
    const uint32_t mb1 = smem_u32(&mbar_s[1]);

    if (tid == 0) { mbar_init(mb0, 1); mbar_init(mb1, 1); }
    __syncthreads();

    // unit t -> gmem source
    auto src_of = [&](int t) -> const float* {
        if (t < 2 * n1) {
            const int j = b + (t >> 1) * G;              // L1 patch
            return feat1 + (size_t)j * 9216 + (size_t)(t & 1) * 4608;
        }
        return feat0 + (size_t)(b + (t - 2 * n1) * G) * 4608;
    };

    // Prologue: fill ring.
    if (tid == 0) {
        if (0 < NU) { mbar_expect_tx(mb0, BYTES); bulk_g2s(bufa,         src_of(0), BYTES, mb0); }
        if (1 < NU) { mbar_expect_tx(mb1, BYTES); bulk_g2s(bufa + BYTES, src_of(1), BYTES, mb1); }
    }

    constexpr float scale = 1.0f / 36.0f;
    int s = 0, phase = 0;

    for (int t = 0; t < NU; t++) {
        mbar_wait(s ? mb1 : mb0, phase);
        const float* bp = buf + s * NFU;
        const bool isL1 = (t < 2 * n1);

        // ---- reduce this unit into fr rows ----
        if (isL1) {
            const int rbase = (t & 1) * 32;              // rows 0..31 or 32..63
            for (int i = tid; i < 288; i += 256) {
                const int crl = i / 9;
                const int p   = i - crl * 9;
                const float* a = bp + crl * 144 + p;     // K=16 groups
                float acc = 0.0f;
#pragma unroll
                for (int q = 0; q < 16; q++) acc += a[q * 9];
                fr[rbase + crl][p] = acc * (1.0f / 16.0f);
            }
        } else {
            for (int i = tid; i < 576; i += 256) {
                const int cr = i / 9;
                const int p  = i - cr * 9;
                const float* a = bp + cr * 72 + p;       // K=8 groups
                float acc = 0.0f;
#pragma unroll
                for (int q = 0; q < 8; q++) acc += a[q * 9];
                fr[cr][p] = acc * (1.0f / 8.0f);
            }
        }
        __syncthreads();    // fr rows ready; buf[s] fully consumed.

        // Re-issue this stage for unit t+S (earliest legal point).
        if (tid == 0 && t + S < NU) {
            const uint32_t mba = s ? mb1 : mb0;
            mbar_expect_tx(mba, BYTES);
            bulk_g2s(bufa + (uint32_t)s * BYTES, src_of(t + S), BYTES, mba);
        }

        // ---- patch complete? (L0 always; L1 after second half) ----
        const bool complete = isL1 ? ((t & 1) != 0) : true;
        if (complete) {
            if (tid < 144) {
                const int g = tid / 9;
                const int p = tid - g * 9;
                sg[g][p] = fr[4 * g + 0][p] + fr[4 * g + 1][p]
                         + fr[4 * g + 2][p] + fr[4 * g + 3][p];
            }
            __syncthreads();

            // epilogue: thread -> (cr, quad), one float4 streaming store
            const int cr = tid >> 2;
            const int q  = tid & 3;
            float frr[9];
#pragma unroll
            for (int p = 0; p < 9; p++) frr[p] = fr[cr][p];

            float4 r4;
            float* rv = &r4.x;
#pragma unroll
            for (int m = 0; m < 4; m++) {
                const int g = q * 4 + m;
                float acc = 0.0f;
#pragma unroll
                for (int p = 0; p < 9; p++)
                    acc += frr[p] * sg[g][p];
                rv[m] = acc * scale;
            }

            size_t obase;
            if (isL1) obase = (size_t)(b + (t >> 1) * G) * 2048 + 1024;
            else      obase = (size_t)(b + (t - 2 * n1) * G) * 2048;
            __stcs(reinterpret_cast<float4*>(out + obase + cr * 16 + q * 4), r4);

            __syncthreads();  // fr/sg consumed before next unit overwrites.
        }

        if (++s == S) { s = 0; phase ^= 1; }
    }
}

extern "C" void kernel_launch(void* const* d_in, const int* in_sizes, int n_in,
                              void* d_out, int out_size)
{
    const float* feat0 = (const float*)d_in[0];   // [N, 512, 3, 3]
    const float* feat1 = (const float*)d_in[1];   // [N, 1024, 3, 3]
    float* out = (float*)d_out;                   // [N, 2, 1024]

    const int N = in_sizes[0] / (512 * 9);

    constexpr int SMEM = 2 * 4608 * 4;            // 36 KB ring
    cudaFuncSetAttribute(fused_gram_kernel,
                         cudaFuncAttributeMaxDynamicSharedMemorySize, SMEM);

    const int GRID = 740;                          // 5 persistent CTAs / SM
    fused_gram_kernel<<<GRID, 256, SMEM>>>(feat0, feat1, out, N);
}

// round 13
// speedup vs baseline: 1.0611x; 1.0611x over previous
#include <cuda_runtime.h>
#include <cstdint>

// R13: register-resident PatchGram. 128 thr/CTA, 5 CTAs/SM, 18KB units,
// conflict-free float4 reduce, shuffle row combine, fr never in smem.
//   out[n][layer][cr*16+g] = (1/(36*K^2)) * sum_p rawfr[cr][p]*rawsg[g][p]

__device__ __forceinline__ uint32_t smem_u32(const void* p) {
    return (uint32_t)__cvta_generic_to_shared(p);
}
__device__ __forceinline__ void mbar_init(uint32_t a, uint32_t cnt) {
    asm volatile("mbarrier.init.shared.b64 [%0], %1;" :: "r"(a), "r"(cnt) : "memory");
}
__device__ __forceinline__ void mbar_expect_tx(uint32_t a, uint32_t bytes) {
    asm volatile("mbarrier.arrive.expect_tx.shared.b64 _, [%0], %1;"
                 :: "r"(a), "r"(bytes) : "memory");
}
__device__ __forceinline__ void mbar_wait(uint32_t a, uint32_t phase) {
    asm volatile(
        "{\n\t"
        ".reg .pred p;\n\t"
        "WAIT_%=:\n\t"
        "mbarrier.try_wait.parity.acquire.cta.shared::cta.b64 p, [%0], %1, 0x989680;\n\t"
        "@p bra DONE_%=;\n\t"
        "bra WAIT_%=;\n\t"
        "DONE_%=:\n\t"
        "}"
        :: "r"(a), "r"(phase) : "memory");
}
__device__ __forceinline__ void bulk_g2s(uint32_t dst_smem, const void* src_gmem,
                                         uint32_t bytes, uint32_t mbar) {
    asm volatile(
        "cp.async.bulk.shared::cluster.global.mbarrier::complete_tx::bytes "
        "[%0], [%1], %2, [%3];"
        :: "r"(dst_smem), "l"(src_gmem), "r"(bytes), "r"(mbar) : "memory");
}

__device__ __forceinline__ float f4c(const float4& v, int c) {
    return c == 0 ? v.x : c == 1 ? v.y : c == 2 ? v.z : v.w;
}

// Emit one output row: o[0..15], from raw row (9 regs) and raw sg block.
__device__ __forceinline__ void emit_row(float* o, const float* row,
                                         const float (*sgb)[12], float sc)
{
#pragma unroll
    for (int g4 = 0; g4 < 4; g4++) {
        float v[4];
#pragma unroll
        for (int m = 0; m < 4; m++) {
            const int g = g4 * 4 + m;
            const float4* sp = reinterpret_cast<const float4*>(&sgb[g][0]);
            const float4 a0 = sp[0];
            const float4 a1 = sp[1];
            const float  a8 = sgb[g][8];
            v[m] = (row[0]*a0.x + row[1]*a0.y + row[2]*a0.z + row[3]*a0.w
                  + row[4]*a1.x + row[5]*a1.y + row[6]*a1.z + row[7]*a1.w
                  + row[8]*a8) * sc;
        }
        float4 r4 = make_float4(v[0], v[1], v[2], v[3]);
        __stcs(reinterpret_cast<float4*>(o) + g4, r4);
    }
}

__global__ __launch_bounds__(128)
void fused_gram_kernel(const float* __restrict__ feat0,
                       const float* __restrict__ feat1,
                       float* __restrict__ out, int N)
{
    constexpr int NFU = 4608;                  // floats per 18KB unit
    constexpr uint32_t BYTES = NFU * 4u;
    constexpr int S = 2;

    extern __shared__ float buf[];             // [S][NFU] = 36 KB
    __shared__ float sg[2][16][12];            // raw sg, patch-parity buffered
    __shared__ alignas(8) unsigned long long mbar_s[S];

    const int tid = threadIdx.x;
    const int b   = blockIdx.x;
    const int G   = gridDim.x;

    const int n1 = (N > b) ? (N - b + G - 1) / G : 0;   // L1 patches (2 units each)
    const int NU = 3 * n1;                               // + n1 L0 patches (1 unit)

    const uint32_t bufa = smem_u32(buf);
    const uint32_t mb0 = smem_u32(&mbar_s[0]);
    const uint32_t mb1 = smem_u32(&mbar_s[1]);

    if (tid == 0) { mbar_init(mb0, 1); mbar_init(mb1, 1); }
    __syncthreads();

    auto src_of = [&](int t) -> const float* {
        if (t < 2 * n1)
            return feat1 + (size_t)(b + (t >> 1) * G) * 9216 + (size_t)(t & 1) * 4608;
        return feat0 + (size_t)(b + (t - 2 * n1) * G) * 4608;
    };

    if (tid == 0) {
        if (0 < NU) { mbar_expect_tx(mb0, BYTES); bulk_g2s(bufa,         src_of(0), BYTES, mb0); }
        if (1 < NU) { mbar_expect_tx(mb1, BYTES); bulk_g2s(bufa + BYTES, src_of(1), BYTES, mb1); }
    }

    float prevrow[9];                           // L1 first-half row (holders)
#pragma unroll
    for (int p = 0; p < 9; p++) prevrow[p] = 0.0f;

    int s = 0, phase = 0;

    for (int t = 0; t < NU; t++) {
        mbar_wait(s ? mb1 : mb0, phase);
        const bool isL1 = (t < 2 * n1);

        // ---- conflict-free vector load: thread covers 4 whole channels ----
        const float4* bp4 = reinterpret_cast<const float4*>(buf + s * NFU) + tid * 9;
        float4 q[9];
#pragma unroll
        for (int j = 0; j < 9; j++) q[j] = bp4[j];

        // fold 36 floats -> 9 partial column sums (4 channels)
        float r[9];
#pragma unroll
        for (int p = 0; p < 9; p++) {
            float a = 0.0f;
#pragma unroll
            for (int k = 0; k < 4; k++) {
                const int e = p + 9 * k;
                a += f4c(q[e >> 2], e & 3);
            }
            r[p] = a;
        }

        // ---- combine to raw fr row + raw sg via shuffles ----
        float row[9], sgv[9];
        int pq;
        if (isL1) {                             // K=16: 4-thread rows, 16-thread sg
#pragma unroll
            for (int p = 0; p < 9; p++) {
                float v = r[p];
                v += __shfl_xor_sync(0xFFFFFFFFu, v, 1);
                v += __shfl_xor_sync(0xFFFFFFFFu, v, 2);
                row[p] = v;
                float w = v;
                w += __shfl_xor_sync(0xFFFFFFFFu, w, 4);
                w += __shfl_xor_sync(0xFFFFFFFFu, w, 8);
                sgv[p] = w;
            }
            pq = (t >> 1) & 1;
            if ((tid & 15) == 0) {
                const int g = (t & 1) * 8 + (tid >> 4);
#pragma unroll
                for (int p = 0; p < 9; p++) sg[pq][g][p] = sgv[p];
            }
        } else {                                // K=8: 2-thread rows, 8-thread sg
#pragma unroll
            for (int p = 0; p < 9; p++) {
                float v = r[p];
                v += __shfl_xor_sync(0xFFFFFFFFu, v, 1);
                row[p] = v;
                float w = v;
                w += __shfl_xor_sync(0xFFFFFFFFu, w, 2);
                w += __shfl_xor_sync(0xFFFFFFFFu, w, 4);
                sgv[p] = w;
            }
            pq = (n1 + (t - 2 * n1)) & 1;       // patch-sequence parity
            if ((tid & 7) == 0) {
                const int g = tid >> 3;
#pragma unroll
                for (int p = 0; p < 9; p++) sg[pq][g][p] = sgv[p];
            }
        }
        __syncthreads();    // sg visible; all buf[s] reads complete.

        // Re-issue this stage for unit t+S.
        if (tid == 0 && t + S < NU) {
            const uint32_t mba = s ? mb1 : mb0;
            mbar_expect_tx(mba, BYTES);
            bulk_g2s(bufa + (uint32_t)s * BYTES, src_of(t + S), BYTES, mba);
        }

        // ---- epilogue (register rows + broadcast sg reads) ----
        if (isL1) {
            if ((t & 1) == 0) {
#pragma unroll
                for (int p = 0; p < 9; p++) prevrow[p] = row[p];
            } else if ((tid & 3) == 0) {
                constexpr float sc = 1.0f / (36.0f * 16.0f * 16.0f);
                const int rloc = tid >> 2;                    // 0..31
                const int j = b + (t >> 1) * G;
                float* o = out + (size_t)j * 2048 + 1024;
                emit_row(o + rloc * 16,        prevrow, sg[pq], sc);
                emit_row(o + (32 + rloc) * 16, row,     sg[pq], sc);
            }
        } else {
            if ((tid & 1) == 0) {
                constexpr float sc = 1.0f / (36.0f * 8.0f * 8.0f);
                const int cr = tid >> 1;                      // 0..63
                const int j = b + (t - 2 * n1) * G;
                float* o = out + (size_t)j * 2048;
                emit_row(o + cr * 16, row, sg[pq], sc);
            }
        }
        // No trailing barrier: next write to sg[pq] is 2 patches away,
        // separated by at least one __syncthreads every thread passes.

        if (++s == S) { s = 0; phase ^= 1; }
    }
}

extern "C" void kernel_launch(void* const* d_in, const int* in_sizes, int n_in,
                              void* d_out, int out_size)
{
    const float* feat0 = (const float*)d_in[0];   // [N, 512, 3, 3]
    const float* feat1 = (const float*)d_in[1];   // [N, 1024, 3, 3]
    float* out = (float*)d_out;                   // [N, 2, 1024]

    const int N = in_sizes[0] / (512 * 9);

    constexpr int SMEM = 2 * 4608 * 4;            // 36 KB ring
    cudaFuncSetAttribute(fused_gram_kernel,
                         cudaFuncAttributeMaxDynamicSharedMemorySize, SMEM);

    const int GRID = 740;                          // 5 persistent CTAs / SM
    fused_gram_kernel<<<GRID, 128, SMEM>>>(feat0, feat1, out, N);
}

// round 14
// speedup vs baseline: 1.1251x; 1.0603x over previous
#include <cuda_runtime.h>
#include <cstdint>

// R14: R13 register-resident PatchGram + dynamic work stealing.
// 128 thr/CTA, 5 CTAs/SM, 18KB units, conflict-free float4 reduce,
// shuffle row combine. Work items pulled from a global atomic counter:
//   item < N      : layer1 patch  (2 units: halves fetched consecutively)
//   N <= item < 2N: layer0 patch  (1 unit)
// Unit descriptor (smem, written by tid0 at refill, read 2 units later):
//   bit0 = isL1, bit1 = half, bits2.. = patch index. 0xFFFFFFFF = no work.

__device__ int g_ctr;
__device__ int g_done;

__device__ __forceinline__ uint32_t smem_u32(const void* p) {
    return (uint32_t)__cvta_generic_to_shared(p);
}
__device__ __forceinline__ void mbar_init(uint32_t a, uint32_t cnt) {
    asm volatile("mbarrier.init.shared.b64 [%0], %1;" :: "r"(a), "r"(cnt) : "memory");
}
__device__ __forceinline__ void mbar_expect_tx(uint32_t a, uint32_t bytes) {
    asm volatile("mbarrier.arrive.expect_tx.shared.b64 _, [%0], %1;"
                 :: "r"(a), "r"(bytes) : "memory");
}
__device__ __forceinline__ void mbar_wait(uint32_t a, uint32_t phase) {
    asm volatile(
        "{\n\t"
        ".reg .pred p;\n\t"
        "WAIT_%=:\n\t"
        "mbarrier.try_wait.parity.acquire.cta.shared::cta.b64 p, [%0], %1, 0x989680;\n\t"
        "@p bra DONE_%=;\n\t"
        "bra WAIT_%=;\n\t"
        "DONE_%=:\n\t"
        "}"
        :: "r"(a), "r"(phase) : "memory");
}
__device__ __forceinline__ void bulk_g2s(uint32_t dst_smem, const void* src_gmem,
                                         uint32_t bytes, uint32_t mbar) {
    asm volatile(
        "cp.async.bulk.shared::cluster.global.mbarrier::complete_tx::bytes "
        "[%0], [%1], %2, [%3];"
        :: "r"(dst_smem), "l"(src_gmem), "r"(bytes), "r"(mbar) : "memory");
}

__device__ __forceinline__ float f4c(const float4& v, int c) {
    return c == 0 ? v.x : c == 1 ? v.y : c == 2 ? v.z : v.w;
}

// Emit one output row o[0..15] from a raw fr row (9 regs) and raw sg block.
__device__ __forceinline__ void emit_row(float* o, const float* row,
                                         const float (*sgb)[12], float sc)
{
#pragma unroll
    for (int g4 = 0; g4 < 4; g4++) {
        float v[4];
#pragma unroll
        for (int m = 0; m < 4; m++) {
            const int g = g4 * 4 + m;
            const float4* sp = reinterpret_cast<const float4*>(&sgb[g][0]);
            const float4 a0 = sp[0];
            const float4 a1 = sp[1];
            const float  a8 = sgb[g][8];
            v[m] = (row[0]*a0.x + row[1]*a0.y + row[2]*a0.z + row[3]*a0.w
                  + row[4]*a1.x + row[5]*a1.y + row[6]*a1.z + row[7]*a1.w
                  + row[8]*a8) * sc;
        }
        __stcs(reinterpret_cast<float4*>(o) + g4,
               make_float4(v[0], v[1], v[2], v[3]));
    }
}

__global__ __launch_bounds__(128)
void fused_gram_kernel(const float* __restrict__ feat0,
                       const float* __restrict__ feat1,
                       float* __restrict__ out, int N)
{
    constexpr int NFU = 4608;                  // floats per 18KB unit
    constexpr uint32_t BYTES = NFU * 4u;
    constexpr uint32_t INV = 0xFFFFFFFFu;

    extern __shared__ float buf[];             // [2][NFU] = 36 KB
    __shared__ float sg[2][16][12];            // raw sg, patch-parity buffered
    __shared__ alignas(8) unsigned long long mbar_s[2];
    __shared__ uint32_t desc_sm[2];

    const int tid = threadIdx.x;
    const uint32_t bufa = smem_u32(buf);
    const uint32_t mb0 = smem_u32(&mbar_s[0]);
    const uint32_t mb1 = smem_u32(&mbar_s[1]);

    // tid0-local item state: pending L1 second half (patch idx, or -1).
    int pend = -1;
    auto fetch_unit = [&]() -> uint32_t {
        if (pend >= 0) { uint32_t d = ((uint32_t)pend << 2) | 2u | 1u; pend = -1; return d; }
        int it = atomicAdd(&g_ctr, 1);
        if (it < N)     { pend = it; return ((uint32_t)it << 2) | 1u; }     // L1 half0
        if (it < 2 * N) { return ((uint32_t)(it - N) << 2); }               // L0 patch
        return INV;
    };
    auto src_of = [&](uint32_t d) -> const float* {
        const int patch = (int)(d >> 2);
        if (d & 1u) return feat1 + (size_t)patch * 9216 + (size_t)((d >> 1) & 1u) * 4608;
        return feat0 + (size_t)patch * 4608;
    };

    if (tid == 0) {
        mbar_init(mb0, 1); mbar_init(mb1, 1);
#pragma unroll
        for (int i = 0; i < 2; i++) {
            uint32_t d = fetch_unit();
            desc_sm[i] = d;
            if (d != INV) {
                const uint32_t mba = i ? mb1 : mb0;
                mbar_expect_tx(mba, BYTES);
                bulk_g2s(bufa + (uint32_t)i * BYTES, src_of(d), BYTES, mba);
            }
        }
    }
    __syncthreads();

    float prevrow[9];
#pragma unroll
    for (int p = 0; p < 9; p++) prevrow[p] = 0.0f;

    int s = 0;
    int ph0 = 0, ph1 = 0;
    int pcnt = 0;                               // completed-patch counter (all threads)

    for (;;) {
        const uint32_t d = desc_sm[s];          // ordered by barrier 2 units ago
        if (d == INV) break;

        if (s == 0) { mbar_wait(mb0, ph0); ph0 ^= 1; }
        else        { mbar_wait(mb1, ph1); ph1 ^= 1; }

        const bool isL1 = (d & 1u) != 0;
        const int  half = (int)((d >> 1) & 1u);
        const int  patch = (int)(d >> 2);
        const int  pq = pcnt & 1;

        // ---- conflict-free vector load: thread covers 4 whole channels ----
        const float4* bp4 = reinterpret_cast<const float4*>(buf + s * NFU) + tid * 9;
        float4 q[9];
#pragma unroll
        for (int j = 0; j < 9; j++) q[j] = bp4[j];

        float r[9];
#pragma unroll
        for (int p = 0; p < 9; p++) {
            float a = 0.0f;
#pragma unroll
            for (int k = 0; k < 4; k++) {
                const int e = p + 9 * k;
                a += f4c(q[e >> 2], e & 3);
            }
            r[p] = a;
        }

        // ---- combine to raw fr row + raw sg via shuffles ----
        float row[9];
        if (isL1) {                             // K=16: 4-thread rows, 16-thread sg
            float sgv[9];
#pragma unroll
            for (int p = 0; p < 9; p++) {
                float v = r[p];
                v += __shfl_xor_sync(0xFFFFFFFFu, v, 1);
                v += __shfl_xor_sync(0xFFFFFFFFu, v, 2);
                row[p] = v;
                float w = v;
                w += __shfl_xor_sync(0xFFFFFFFFu, w, 4);
                w += __shfl_xor_sync(0xFFFFFFFFu, w, 8);
                sgv[p] = w;
            }
            if ((tid & 15) == 0) {
                const int g = half * 8 + (tid >> 4);
#pragma unroll
                for (int p = 0; p < 9; p++) sg[pq][g][p] = sgv[p];
            }
        } else {                                // K=8: 2-thread rows, 8-thread sg
            float sgv[9];
#pragma unroll
            for (int p = 0; p < 9; p++) {
                float v = r[p];
                v += __shfl_xor_sync(0xFFFFFFFFu, v, 1);
                row[p] = v;
                float w = v;
                w += __shfl_xor_sync(0xFFFFFFFFu, w, 2);
                w += __shfl_xor_sync(0xFFFFFFFFu, w, 4);
                sgv[p] = w;
            }
            if ((tid & 7) == 0) {
                const int g = tid >> 3;
#pragma unroll
                for (int p = 0; p < 9; p++) sg[pq][g][p] = sgv[p];
            }
        }
        __syncthreads();    // sg visible; all buf[s] reads complete.

        // ---- re-arm this stage with the next dynamically-fetched unit ----
        if (tid == 0) {
            const uint32_t nd = fetch_unit();
            desc_sm[s] = nd;
            if (nd != INV) {
                const uint32_t mba = s ? mb1 : mb0;
                mbar_expect_tx(mba, BYTES);
                bulk_g2s(bufa + (uint32_t)s * BYTES, src_of(nd), BYTES, mba);
            }
        }

        // ---- epilogue (register rows + broadcast sg reads) ----
        if (isL1) {
            if (half == 0) {
#pragma unroll
                for (int p = 0; p < 9; p++) prevrow[p] = row[p];
            } else if ((tid & 3) == 0) {
                constexpr float sc = 1.0f / (36.0f * 16.0f * 16.0f);
                const int rloc = tid >> 2;                    // 0..31
                float* o = out + (size_t)patch * 2048 + 1024;
                emit_row(o + rloc * 16,        prevrow, sg[pq], sc);
                emit_row(o + (32 + rloc) * 16, row,     sg[pq], sc);
            }
        } else {
            if ((tid & 1) == 0) {
                constexpr float sc = 1.0f / (36.0f * 8.0f * 8.0f);
                const int cr = tid >> 1;                      // 0..63
                float* o = out + (size_t)patch * 2048;
                emit_row(o + cr * 16, row, sg[pq], sc);
            }
        }
        // No trailing barrier: next write to sg[pq] is 2 patches away,
        // separated by at least one __syncthreads every thread passes.

        if (!isL1 || half) pcnt++;
        s ^= 1;
    }

    // ---- counter reset for the next launch: last CTA to finish cleans up ----
    if (tid == 0) {
        __threadfence();
        const int dcnt = atomicAdd(&g_done, 1);
        if (dcnt == (int)gridDim.x - 1) {
            atomicExch(&g_ctr, 0);
            __threadfence();
            atomicExch(&g_done, 0);
        }
    }
}

extern "C" void kernel_launch(void* const* d_in, const int* in_sizes, int n_in,
                              void* d_out, int out_size)
{
    const float* feat0 = (const float*)d_in[0];   // [N, 512, 3, 3]
    const float* feat1 = (const float*)d_in[1];   // [N, 1024, 3, 3]
    float* out = (float*)d_out;                   // [N, 2, 1024]

    const int N = in_sizes[0] / (512 * 9);

    constexpr int SMEM = 2 * 4608 * 4;            // 36 KB ring
    cudaFuncSetAttribute(fused_gram_kernel,
                         cudaFuncAttributeMaxDynamicSharedMemorySize, SMEM);

    const int GRID = 740;                          // 5 persistent CTAs / SM
    fused_gram_kernel<<<GRID, 128, SMEM>>>(feat0, feat1, out, N);
}